// round 3
// baseline (speedup 1.0000x reference)
#include <cuda_runtime.h>

#define BB 8
#define HH 128
#define WWD 128
#define DD 512
#define DD4 128          // D / 4
#define CHUNK_B 2        // batches per L2 chunk
#define NCHUNK (BB / CHUNK_B)

// Scratch (allocation-free rule: __device__ globals)
__device__ float4 g_partial[BB * HH * 5 * DD4];  // [b][h][k][d4], k=0..3 w-region sums, k=4 full row
__device__ float4 g_sums[BB * 17 * DD4];         // [b][r][d4], r=0..15 region sums, r=16 global

__device__ __forceinline__ float4 f4add(float4 a, float4 b) {
    return make_float4(a.x + b.x, a.y + b.y, a.z + b.z, a.w + b.w);
}
__device__ __forceinline__ float4 f4fma(float s, float4 a, float4 b) {
    return make_float4(fmaf(s, a.x, b.x), fmaf(s, a.y, b.y),
                       fmaf(s, a.z, b.z), fmaf(s, a.w, b.w));
}

// ---------------------------------------------------------------------------
// k1: per (b,h) row — accumulate per-w-region partial sums + full row sum.
// grid = CHUNK_B*H blocks, 128 threads (one float4 d-lane each).
// Segmented w-loops: constant region membership per segment (no predicates).
// ---------------------------------------------------------------------------
__global__ __launch_bounds__(128) void k1_rowsums(const float4* __restrict__ feat,
                                                  int bh0) {
    const int bh = bh0 + blockIdx.x;
    const int t  = threadIdx.x;
    const float4* row = feat + (size_t)bh * WWD * DD4 + t;

    float4 a0 = make_float4(0.f, 0.f, 0.f, 0.f);
    float4 a1 = a0, a2 = a0, a3 = a0, af = a0;

    // region j covers w in [24j, 24j+32)
    #pragma unroll 8
    for (int w = 0; w < 24; ++w)   { float4 v = __ldg(&row[(size_t)w * DD4]); af = f4add(af, v); a0 = f4add(a0, v); }
    #pragma unroll 8
    for (int w = 24; w < 32; ++w)  { float4 v = __ldg(&row[(size_t)w * DD4]); af = f4add(af, v); a0 = f4add(a0, v); a1 = f4add(a1, v); }
    #pragma unroll 8
    for (int w = 32; w < 48; ++w)  { float4 v = __ldg(&row[(size_t)w * DD4]); af = f4add(af, v); a1 = f4add(a1, v); }
    #pragma unroll 8
    for (int w = 48; w < 56; ++w)  { float4 v = __ldg(&row[(size_t)w * DD4]); af = f4add(af, v); a1 = f4add(a1, v); a2 = f4add(a2, v); }
    #pragma unroll 8
    for (int w = 56; w < 72; ++w)  { float4 v = __ldg(&row[(size_t)w * DD4]); af = f4add(af, v); a2 = f4add(a2, v); }
    #pragma unroll 8
    for (int w = 72; w < 80; ++w)  { float4 v = __ldg(&row[(size_t)w * DD4]); af = f4add(af, v); a2 = f4add(a2, v); a3 = f4add(a3, v); }
    #pragma unroll 8
    for (int w = 80; w < 104; ++w) { float4 v = __ldg(&row[(size_t)w * DD4]); af = f4add(af, v); a3 = f4add(a3, v); }
    #pragma unroll 8
    for (int w = 104; w < 128; ++w){ float4 v = __ldg(&row[(size_t)w * DD4]); af = f4add(af, v); }

    float4* p = g_partial + (size_t)bh * 5 * DD4 + t;
    p[0 * DD4] = a0;
    p[1 * DD4] = a1;
    p[2 * DD4] = a2;
    p[3 * DD4] = a3;
    p[4 * DD4] = af;
}

// ---------------------------------------------------------------------------
// k1b: reduce partials over h into 16 region sums + global sum.
// grid = CHUNK_B*17 blocks, 128 threads.
// ---------------------------------------------------------------------------
__global__ __launch_bounds__(128) void k1b_reduce(int b0) {
    const int b = b0 + blockIdx.x / 17;
    const int r = blockIdx.x % 17;
    const int t = threadIdx.x;

    float4 acc = make_float4(0.f, 0.f, 0.f, 0.f);
    if (r < 16) {
        const int i  = r >> 2;     // h-region index
        const int j  = r & 3;      // w-region index
        const int h0 = 24 * i;     // h-region covers [24i, 24i+32)
        #pragma unroll 8
        for (int hh = 0; hh < 32; ++hh) {
            float4 v = g_partial[((size_t)(b * HH + h0 + hh) * 5 + j) * DD4 + t];
            acc = f4add(acc, v);
        }
    } else {
        #pragma unroll 8
        for (int h = 0; h < HH; ++h) {
            float4 v = g_partial[((size_t)(b * HH + h) * 5 + 4) * DD4 + t];
            acc = f4add(acc, v);
        }
    }
    g_sums[(size_t)(b * 17 + r) * DD4 + t] = acc;
}

// ---------------------------------------------------------------------------
// k2: elementwise pass. grid = CHUNK_B*H blocks, 512 threads:
//   threadIdx = wq*128 + t  (wq = w-quarter 0..3, t = d4 lane 0..127)
// Separable weights: agg = Σ_j (ww[j,w]*coef[h,w]) * colagg[j,d]
//   colagg[j,d] = Σ_i hw[i,h] * regionsum[i*4+j,d]
//   coef[h,w]   = 0.6 / (1024 * (HS[h]*WS[w] + 1e-8))
// Per-w weight*coef packed as one float4 in shared.
// ---------------------------------------------------------------------------
__global__ __launch_bounds__(512) void k2_apply(const float4* __restrict__ feat,
                                                float4* __restrict__ out,
                                                int bh0) {
    const int bh = bh0 + blockIdx.x;
    const int b  = bh >> 7;
    const int h  = bh & 127;
    const int t  = threadIdx.x & 127;   // d4 lane
    const int wq = threadIdx.x >> 7;    // w quarter

    __shared__ float4 s_wc[WWD];        // {ww0,ww1,ww2,ww3} * coef, per w

    // per-h Gaussian weights (uniform across block, cheap)
    const float hc = h * (3.0f / 127.0f);
    float hwv[4];
    float HS = 0.f;
    #pragma unroll
    for (int i = 0; i < 4; ++i) {
        float d = hc - (float)i;
        hwv[i] = __expf(-0.125f * d * d);
        HS += hwv[i];
    }

    // per-w tables into shared (one thread per w)
    if (threadIdx.x < WWD) {
        const int w = threadIdx.x;
        const float wc = w * (3.0f / 127.0f);
        float e[4];
        float WS = 0.f;
        #pragma unroll
        for (int j = 0; j < 4; ++j) {
            float d = wc - (float)j;
            e[j] = __expf(-0.125f * d * d);
            WS += e[j];
        }
        const float c = 0.6f / (1024.0f * (HS * WS + 1e-8f));
        s_wc[w] = make_float4(e[0] * c, e[1] * c, e[2] * c, e[3] * c);
    }
    __syncthreads();

    // colagg[j] and global term for this d4 lane (g_sums is tiny; L2-hot)
    const float4* srow = g_sums + (size_t)b * 17 * DD4 + t;
    float4 ca[4];
    #pragma unroll
    for (int j = 0; j < 4; ++j) ca[j] = make_float4(0.f, 0.f, 0.f, 0.f);
    #pragma unroll
    for (int i = 0; i < 4; ++i) {
        #pragma unroll
        for (int j = 0; j < 4; ++j) {
            float4 s = srow[(i * 4 + j) * DD4];
            ca[j] = f4fma(hwv[i], s, ca[j]);
        }
    }
    float4 gs = srow[16 * DD4];
    const float gscale = 0.4f / 16384.0f;
    float4 base = make_float4(gs.x * gscale, gs.y * gscale, gs.z * gscale, gs.w * gscale);

    const float4* frow = feat + (size_t)bh * WWD * DD4 + t;
    float4*       orow = out  + (size_t)bh * WWD * DD4 + t;

    const int w0 = wq * 32;
    #pragma unroll 8
    for (int wi = 0; wi < 32; ++wi) {
        const int w = w0 + wi;
        float4 v  = __ldg(&frow[(size_t)w * DD4]);
        float4 wc = s_wc[w];

        float4 r;
        r.x = v.x + base.x + wc.x * ca[0].x + wc.y * ca[1].x + wc.z * ca[2].x + wc.w * ca[3].x;
        r.y = v.y + base.y + wc.x * ca[0].y + wc.y * ca[1].y + wc.z * ca[2].y + wc.w * ca[3].y;
        r.z = v.z + base.z + wc.x * ca[0].z + wc.y * ca[1].z + wc.z * ca[2].z + wc.w * ca[3].z;
        r.w = v.w + base.w + wc.x * ca[0].w + wc.y * ca[1].w + wc.z * ca[2].w + wc.w * ca[3].w;
        orow[(size_t)w * DD4] = r;
    }
}

// ---------------------------------------------------------------------------
// Chunked schedule: for each 2-batch chunk, reduce then apply while the
// chunk's features are still L2-resident (64 MiB feat + 64 MiB out < 126 MB L2).
// DRAM traffic drops from 768 MiB to ~512 MiB.
// ---------------------------------------------------------------------------
extern "C" void kernel_launch(void* const* d_in, const int* in_sizes, int n_in,
                              void* d_out, int out_size) {
    const float4* feat = (const float4*)d_in[0];
    float4*       out  = (float4*)d_out;

    for (int c = 0; c < NCHUNK; ++c) {
        const int b0  = c * CHUNK_B;
        const int bh0 = b0 * HH;
        k1_rowsums<<<CHUNK_B * HH, 128>>>(feat, bh0);
        k1b_reduce<<<CHUNK_B * 17, 128>>>(b0);
        k2_apply<<<CHUNK_B * HH, 512>>>(feat, out, bh0);
    }
}

// round 4
// speedup vs baseline: 1.3970x; 1.3970x over previous
#include <cuda_runtime.h>

#define BB 8
#define HH 128
#define WWD 128
#define DD4 128          // D / 4 (float4 lanes)
#define CHUNK_B 2        // batches per L2 chunk
#define NCHUNK (BB / CHUNK_B)
#define CROWS (CHUNK_B * HH)   // 256 rows per chunk

// Scratch (allocation-free rule: __device__ globals)
// g_seg: per chunk-local row, 16 segment sums of 8 w each. 256*16*2KB = 8 MiB.
__device__ float4 g_seg[CROWS * 16 * DD4];
// g_sums: per batch, 32 items: 0..15 region sums (i*4+j), 16..31 global parts.
__device__ float4 g_sums[BB * 32 * DD4];

__device__ __forceinline__ float4 f4add(float4 a, float4 b) {
    return make_float4(a.x + b.x, a.y + b.y, a.z + b.z, a.w + b.w);
}
__device__ __forceinline__ float4 f4fma(float s, float4 a, float4 b) {
    return make_float4(fmaf(s, a.x, b.x), fmaf(s, a.y, b.y),
                       fmaf(s, a.z, b.z), fmaf(s, a.w, b.w));
}

// ---------------------------------------------------------------------------
// k1: item = (chunk-row, w-quarter). grid = CROWS*4 = 1024 blocks, 128 threads.
// Each block reads its 32-w slice once and writes 4 seg sums (8 w each).
// ---------------------------------------------------------------------------
__global__ __launch_bounds__(128) void k1_segsums(const float4* __restrict__ feat,
                                                  int bh0) {
    const int row = blockIdx.x >> 2;   // chunk-local row
    const int q   = blockIdx.x & 3;    // w quarter
    const int t   = threadIdx.x;
    const int bh  = bh0 + row;

    const float4* p = feat + ((size_t)bh * WWD + q * 32) * DD4 + t;
    float4* o = g_seg + ((size_t)row * 16 + q * 4) * DD4 + t;

    #pragma unroll
    for (int s = 0; s < 4; ++s) {
        float4 a = make_float4(0.f, 0.f, 0.f, 0.f);
        #pragma unroll
        for (int w = 0; w < 8; ++w)
            a = f4add(a, __ldg(&p[(size_t)(s * 8 + w) * DD4]));
        o[(size_t)s * DD4] = a;
    }
}

// ---------------------------------------------------------------------------
// k1b: grid = CHUNK_B*32 blocks, 128 threads. Every item = 32 rows x 4 segs
// (128 L2-hot float4 loads per thread).
//   item < 16 : region (i = item>>2, j = item&3), h in [24i,24i+32), segs 3j..3j+3
//   item >= 16: global part p = item-16: h-band (p>>2)*32, seg-band (p&3)*4
// ---------------------------------------------------------------------------
__global__ __launch_bounds__(128) void k1b_reduce(int b0) {
    const int b_local = blockIdx.x >> 5;
    const int item    = blockIdx.x & 31;
    const int t       = threadIdx.x;

    int row0, seg0;
    if (item < 16) {
        row0 = b_local * HH + 24 * (item >> 2);
        seg0 = 3 * (item & 3);
    } else {
        const int p = item - 16;
        row0 = b_local * HH + 32 * (p >> 2);
        seg0 = 4 * (p & 3);
    }

    float4 acc = make_float4(0.f, 0.f, 0.f, 0.f);
    #pragma unroll 4
    for (int hh = 0; hh < 32; ++hh) {
        const float4* base = g_seg + ((size_t)(row0 + hh) * 16 + seg0) * DD4 + t;
        #pragma unroll
        for (int s = 0; s < 4; ++s)
            acc = f4add(acc, base[(size_t)s * DD4]);
    }
    g_sums[((size_t)(b0 + b_local) * 32 + item) * DD4 + t] = acc;
}

// ---------------------------------------------------------------------------
// k2: item = (chunk-row, w-quarter). grid = CROWS*4 = 1024 blocks, 128 threads.
// Separable weights:
//   out = feat + 0.4*gsum/16384 + sum_j (ww[j,w]*coef[h,w]) * colagg[j,d]
//   colagg[j,d] = sum_i hw[i,h] * regionsum[i*4+j,d]
//   coef[h,w]   = 0.6 / (1024 * (HS[h]*WS[w] + 1e-8))
// Streaming stores (__stcs) keep output from evicting L2-resident features.
// ---------------------------------------------------------------------------
__global__ __launch_bounds__(128) void k2_apply(const float4* __restrict__ feat,
                                                float4* __restrict__ out,
                                                int bh0) {
    const int row = blockIdx.x >> 2;
    const int q   = blockIdx.x & 3;
    const int t   = threadIdx.x;
    const int bh  = bh0 + row;
    const int b   = bh >> 7;
    const int h   = bh & 127;

    __shared__ float4 s_wc[32];   // {ww0..ww3}*coef for this block's 32 w

    // per-h Gaussian weights (uniform across block)
    const float hc = h * (3.0f / 127.0f);
    float hwv[4];
    float HS = 0.f;
    #pragma unroll
    for (int i = 0; i < 4; ++i) {
        float d = hc - (float)i;
        hwv[i] = __expf(-0.125f * d * d);
        HS += hwv[i];
    }

    if (t < 32) {
        const int w = q * 32 + t;
        const float wc = w * (3.0f / 127.0f);
        float e[4];
        float WS = 0.f;
        #pragma unroll
        for (int j = 0; j < 4; ++j) {
            float d = wc - (float)j;
            e[j] = __expf(-0.125f * d * d);
            WS += e[j];
        }
        const float c = 0.6f / (1024.0f * (HS * WS + 1e-8f));
        s_wc[t] = make_float4(e[0] * c, e[1] * c, e[2] * c, e[3] * c);
    }
    __syncthreads();

    // colagg[j] and global sum for this d4 lane (g_sums tiny, L2-hot)
    const float4* srow = g_sums + (size_t)b * 32 * DD4 + t;
    float4 ca[4];
    #pragma unroll
    for (int j = 0; j < 4; ++j) ca[j] = make_float4(0.f, 0.f, 0.f, 0.f);
    #pragma unroll
    for (int i = 0; i < 4; ++i)
        #pragma unroll
        for (int j = 0; j < 4; ++j)
            ca[j] = f4fma(hwv[i], srow[(i * 4 + j) * DD4], ca[j]);

    float4 gsum = make_float4(0.f, 0.f, 0.f, 0.f);
    #pragma unroll
    for (int p = 0; p < 16; ++p)
        gsum = f4add(gsum, srow[(16 + p) * DD4]);
    const float gscale = 0.4f / 16384.0f;
    float4 base = make_float4(gsum.x * gscale, gsum.y * gscale,
                              gsum.z * gscale, gsum.w * gscale);

    const float4* frow = feat + ((size_t)bh * WWD + q * 32) * DD4 + t;
    float4*       orow = out  + ((size_t)bh * WWD + q * 32) * DD4 + t;

    #pragma unroll 8
    for (int wi = 0; wi < 32; ++wi) {
        float4 v  = __ldg(&frow[(size_t)wi * DD4]);
        float4 wc = s_wc[wi];
        float4 r;
        r.x = v.x + base.x + wc.x * ca[0].x + wc.y * ca[1].x + wc.z * ca[2].x + wc.w * ca[3].x;
        r.y = v.y + base.y + wc.x * ca[0].y + wc.y * ca[1].y + wc.z * ca[2].y + wc.w * ca[3].y;
        r.z = v.z + base.z + wc.x * ca[0].z + wc.y * ca[1].z + wc.z * ca[2].z + wc.w * ca[3].z;
        r.w = v.w + base.w + wc.x * ca[0].w + wc.y * ca[1].w + wc.z * ca[2].w + wc.w * ca[3].w;
        __stcs(&orow[(size_t)wi * DD4], r);
    }
}

// ---------------------------------------------------------------------------
// Chunked schedule with FULL grids per launch (R3's failure was grid shrink).
// Per chunk (2 batches, 64 MiB): k1 streams feat into L2, k1b reduces (tiny),
// k2 re-reads feat from L2 and streams output to DRAM.
// ---------------------------------------------------------------------------
extern "C" void kernel_launch(void* const* d_in, const int* in_sizes, int n_in,
                              void* d_out, int out_size) {
    const float4* feat = (const float4*)d_in[0];
    float4*       out  = (float4*)d_out;

    for (int c = 0; c < NCHUNK; ++c) {
        const int b0  = c * CHUNK_B;
        const int bh0 = b0 * HH;
        k1_segsums<<<CROWS * 4, 128>>>(feat, bh0);
        k1b_reduce<<<CHUNK_B * 32, 128>>>(b0);
        k2_apply<<<CROWS * 4, 128>>>(feat, out, bh0);
    }
}

// round 5
// speedup vs baseline: 1.6807x; 1.2031x over previous
#include <cuda_runtime.h>

#define BB 8
#define HH 128
#define WWD 128
#define DD4 128          // D / 4 (float4 lanes)

// Scratch (allocation-free rule: __device__ globals)
__device__ float4 g_partial[BB * HH * 5 * DD4];  // [b][h][k][d4], k=0..3 w-region sums, k=4 full row
__device__ float4 g_sums[BB * 17 * DD4];         // [b][r][d4], r=0..15 region sums, r=16 global

__device__ __forceinline__ float4 f4add(float4 a, float4 b) {
    return make_float4(a.x + b.x, a.y + b.y, a.z + b.z, a.w + b.w);
}
__device__ __forceinline__ float4 f4fma(float s, float4 a, float4 b) {
    return make_float4(fmaf(s, a.x, b.x), fmaf(s, a.y, b.y),
                       fmaf(s, a.z, b.z), fmaf(s, a.w, b.w));
}

// ---------------------------------------------------------------------------
// k1: per (b,h) row — per-w-region partial sums + full row sum.
// grid = B*H = 1024 blocks, 128 threads. Proven geometry (R2: 5.96 TB/s).
// Segmented w-loops: constant region membership per segment (no predicates).
// ---------------------------------------------------------------------------
__global__ __launch_bounds__(128) void k1_rowsums(const float4* __restrict__ feat) {
    const int bh = blockIdx.x;
    const int t  = threadIdx.x;
    const float4* row = feat + (size_t)bh * WWD * DD4 + t;

    float4 a0 = make_float4(0.f, 0.f, 0.f, 0.f);
    float4 a1 = a0, a2 = a0, a3 = a0, af = a0;

    // region j covers w in [24j, 24j+32)
    #pragma unroll 8
    for (int w = 0; w < 24; ++w)   { float4 v = __ldg(&row[(size_t)w * DD4]); af = f4add(af, v); a0 = f4add(a0, v); }
    #pragma unroll 8
    for (int w = 24; w < 32; ++w)  { float4 v = __ldg(&row[(size_t)w * DD4]); af = f4add(af, v); a0 = f4add(a0, v); a1 = f4add(a1, v); }
    #pragma unroll 8
    for (int w = 32; w < 48; ++w)  { float4 v = __ldg(&row[(size_t)w * DD4]); af = f4add(af, v); a1 = f4add(a1, v); }
    #pragma unroll 8
    for (int w = 48; w < 56; ++w)  { float4 v = __ldg(&row[(size_t)w * DD4]); af = f4add(af, v); a1 = f4add(a1, v); a2 = f4add(a2, v); }
    #pragma unroll 8
    for (int w = 56; w < 72; ++w)  { float4 v = __ldg(&row[(size_t)w * DD4]); af = f4add(af, v); a2 = f4add(a2, v); }
    #pragma unroll 8
    for (int w = 72; w < 80; ++w)  { float4 v = __ldg(&row[(size_t)w * DD4]); af = f4add(af, v); a2 = f4add(a2, v); a3 = f4add(a3, v); }
    #pragma unroll 8
    for (int w = 80; w < 104; ++w) { float4 v = __ldg(&row[(size_t)w * DD4]); af = f4add(af, v); a3 = f4add(a3, v); }
    #pragma unroll 8
    for (int w = 104; w < 128; ++w){ float4 v = __ldg(&row[(size_t)w * DD4]); af = f4add(af, v); }

    float4* p = g_partial + (size_t)bh * 5 * DD4 + t;
    p[0 * DD4] = a0;
    p[1 * DD4] = a1;
    p[2 * DD4] = a2;
    p[3 * DD4] = a3;
    p[4 * DD4] = af;
}

// ---------------------------------------------------------------------------
// k1b: reduce partials over h into 16 region sums + global sum.
// grid = B*17 blocks, 128 threads. ~10 MiB read, L2-resident, ~3 us.
// ---------------------------------------------------------------------------
__global__ __launch_bounds__(128) void k1b_reduce() {
    const int b = blockIdx.x / 17;
    const int r = blockIdx.x % 17;
    const int t = threadIdx.x;

    float4 acc = make_float4(0.f, 0.f, 0.f, 0.f);
    if (r < 16) {
        const int i  = r >> 2;     // h-region index
        const int j  = r & 3;      // w-region index
        const int h0 = 24 * i;     // h-region covers [24i, 24i+32)
        #pragma unroll 8
        for (int hh = 0; hh < 32; ++hh) {
            float4 v = g_partial[((size_t)(b * HH + h0 + hh) * 5 + j) * DD4 + t];
            acc = f4add(acc, v);
        }
    } else {
        #pragma unroll 8
        for (int h = 0; h < HH; ++h) {
            float4 v = g_partial[((size_t)(b * HH + h) * 5 + 4) * DD4 + t];
            acc = f4add(acc, v);
        }
    }
    g_sums[(size_t)(b * 17 + r) * DD4 + t] = acc;
}

// ---------------------------------------------------------------------------
// k2: elementwise pass, 8-deep explicit load batching for MLP.
// grid = B*H = 1024 blocks, 512 threads: threadIdx = wq*128 + t.
// Separable weights: out = feat + 0.4*gmean + sum_j (ww[j,w]*coef[h,w])*colagg[j,d]
//   colagg[j,d] = sum_i hw[i,h] * regionsum[i*4+j,d]
//   coef[h,w]   = 0.6 / (1024 * (HS[h]*WS[w] + 1e-8))
// ---------------------------------------------------------------------------
__global__ __launch_bounds__(512) void k2_apply(const float4* __restrict__ feat,
                                                float4* __restrict__ out) {
    const int bh = blockIdx.x;
    const int b  = bh >> 7;
    const int h  = bh & 127;
    const int t  = threadIdx.x & 127;   // d4 lane
    const int wq = threadIdx.x >> 7;    // w quarter

    __shared__ float4 s_wc[WWD];        // {ww0..ww3} * coef, per w

    // per-h Gaussian weights (uniform across block)
    const float hc = h * (3.0f / 127.0f);
    float hwv[4];
    float HS = 0.f;
    #pragma unroll
    for (int i = 0; i < 4; ++i) {
        float d = hc - (float)i;
        hwv[i] = __expf(-0.125f * d * d);
        HS += hwv[i];
    }

    if (threadIdx.x < WWD) {
        const int w = threadIdx.x;
        const float wc = w * (3.0f / 127.0f);
        float e[4];
        float WS = 0.f;
        #pragma unroll
        for (int j = 0; j < 4; ++j) {
            float d = wc - (float)j;
            e[j] = __expf(-0.125f * d * d);
            WS += e[j];
        }
        const float c = 0.6f / (1024.0f * (HS * WS + 1e-8f));
        s_wc[w] = make_float4(e[0] * c, e[1] * c, e[2] * c, e[3] * c);
    }
    __syncthreads();

    // colagg[j] + global term for this d4 lane (g_sums tiny, L2-hot)
    const float4* srow = g_sums + (size_t)b * 17 * DD4 + t;
    float4 ca[4];
    #pragma unroll
    for (int j = 0; j < 4; ++j) ca[j] = make_float4(0.f, 0.f, 0.f, 0.f);
    #pragma unroll
    for (int i = 0; i < 4; ++i)
        #pragma unroll
        for (int j = 0; j < 4; ++j)
            ca[j] = f4fma(hwv[i], srow[(i * 4 + j) * DD4], ca[j]);

    float4 gs = srow[16 * DD4];
    const float gscale = 0.4f / 16384.0f;
    float4 base = make_float4(gs.x * gscale, gs.y * gscale, gs.z * gscale, gs.w * gscale);

    const float4* frow = feat + ((size_t)bh * WWD + wq * 32) * DD4 + t;
    float4*       orow = out  + ((size_t)bh * WWD + wq * 32) * DD4 + t;
    const int w0 = wq * 32;

    // 4 groups of 8: front-batch 8 independent LDG.128, then compute+store 8.
    #pragma unroll
    for (int g = 0; g < 4; ++g) {
        float4 v[8];
        #pragma unroll
        for (int k = 0; k < 8; ++k)
            v[k] = __ldg(&frow[(size_t)(g * 8 + k) * DD4]);

        #pragma unroll
        for (int k = 0; k < 8; ++k) {
            const float4 wc = s_wc[w0 + g * 8 + k];
            float4 r;
            r.x = v[k].x + base.x + wc.x * ca[0].x + wc.y * ca[1].x + wc.z * ca[2].x + wc.w * ca[3].x;
            r.y = v[k].y + base.y + wc.x * ca[0].y + wc.y * ca[1].y + wc.z * ca[2].y + wc.w * ca[3].y;
            r.z = v[k].z + base.z + wc.x * ca[0].z + wc.y * ca[1].z + wc.z * ca[2].z + wc.w * ca[3].z;
            r.w = v[k].w + base.w + wc.x * ca[0].w + wc.y * ca[1].w + wc.z * ca[2].w + wc.w * ca[3].w;
            __stcs(&orow[(size_t)(g * 8 + k) * DD4], r);
        }
    }
}

// ---------------------------------------------------------------------------
// Monolithic schedule (R2 structure — chunking measured slower twice).
// ---------------------------------------------------------------------------
extern "C" void kernel_launch(void* const* d_in, const int* in_sizes, int n_in,
                              void* d_out, int out_size) {
    const float4* feat = (const float4*)d_in[0];
    float4*       out  = (float4*)d_out;

    k1_rowsums<<<BB * HH, 128>>>(feat);
    k1b_reduce<<<BB * 17, 128>>>();
    k2_apply<<<BB * HH, 512>>>(feat, out);
}